// round 1
// baseline (speedup 1.0000x reference)
#include <cuda_runtime.h>
#include <cuda_bf16.h>
#include <math.h>

#define BB 8
#define SS 1024
#define DD 512
#define HH 8
#define WW 8
#define DKK 64
#define SP2 1040   // S + 2*WIDTH
#define DD2 1024   // 2*D

// ---------------- scratch (static device allocations) ----------------
__device__ float g_newin[(size_t)BB * SP2 * DD];   // padded input
__device__ float g_q[(size_t)BB * SP2 * DD];
__device__ float g_k[(size_t)BB * SP2 * DD];
__device__ float g_v[(size_t)BB * SP2 * DD];
__device__ float g_attn[(size_t)BB * SS * DD];     // banded attention output (compact S rows)
__device__ float g_x[(size_t)BB * SS * DD];        // highway running state
__device__ float g_proj[(size_t)BB * SS * DD2];    // highway projection scratch

// ---------------- build padded input ----------------
__global__ void k_build_newin(const float* __restrict__ x,
                              const float* __restrict__ lpad,
                              const float* __restrict__ rpad)
{
    int idx = blockIdx.x * blockDim.x + threadIdx.x;   // over B*S2*D/4
    int total = BB * SP2 * (DD / 4);
    if (idx >= total) return;
    int d4 = idx % (DD / 4);
    int s  = (idx / (DD / 4)) % SP2;
    int b  = idx / ((DD / 4) * SP2);

    float4 v;
    if (s < WW) {
        v = ((const float4*)(lpad + (size_t)s * DD))[d4];
    } else if (s < WW + SS) {
        v = ((const float4*)(x + ((size_t)b * SS + (s - WW)) * DD))[d4];
    } else {
        v = ((const float4*)(rpad + (size_t)(s - WW - SS) * DD))[d4];
    }
    ((float4*)(g_newin + ((size_t)b * SP2 + s) * DD))[d4] = v;
}

// ---------------- classic tiled SGEMM: C[M,N] = A[M,K] @ W[K,N] + bias ----------------
// M % 128 == 0, N % 128 == 0, K % 8 == 0 (guaranteed by shapes here)
__global__ void __launch_bounds__(256)
k_sgemm(const float* __restrict__ A, const float* __restrict__ Wm,
        const float* __restrict__ bias, float* __restrict__ C,
        int M, int N, int K)
{
    __shared__ float As[8][128];
    __shared__ float Bs[8][128];

    int tid = threadIdx.x;
    int m0 = blockIdx.y * 128;
    int n0 = blockIdx.x * 128;

    int arow = tid >> 1;            // 0..127
    int akk  = (tid & 1) * 4;       // 0 or 4
    int bkk  = tid >> 5;            // 0..7
    int bcol = (tid & 31) * 4;      // 0..124

    int tx = tid & 15;              // 0..15
    int ty = tid >> 4;              // 0..15

    float acc[8][8];
#pragma unroll
    for (int i = 0; i < 8; i++)
#pragma unroll
        for (int j = 0; j < 8; j++) acc[i][j] = 0.f;

    const float* Aptr = A + (size_t)(m0 + arow) * K + akk;
    const float* Bptr = Wm + (size_t)bkk * N + n0 + bcol;

    for (int k0 = 0; k0 < K; k0 += 8) {
        float4 av = *(const float4*)Aptr;
        float4 bv = *(const float4*)Bptr;
        As[akk + 0][arow] = av.x;
        As[akk + 1][arow] = av.y;
        As[akk + 2][arow] = av.z;
        As[akk + 3][arow] = av.w;
        *(float4*)&Bs[bkk][bcol] = bv;
        __syncthreads();

#pragma unroll
        for (int kk = 0; kk < 8; kk++) {
            float a[8], b[8];
#pragma unroll
            for (int i = 0; i < 8; i++) a[i] = As[kk][ty * 8 + i];
#pragma unroll
            for (int j = 0; j < 8; j++) b[j] = Bs[kk][tx * 8 + j];
#pragma unroll
            for (int i = 0; i < 8; i++)
#pragma unroll
                for (int j = 0; j < 8; j++)
                    acc[i][j] = fmaf(a[i], b[j], acc[i][j]);
        }
        __syncthreads();

        Aptr += 8;
        Bptr += (size_t)8 * N;
    }

#pragma unroll
    for (int i = 0; i < 8; i++) {
        int m = m0 + ty * 8 + i;
        float* crow = C + (size_t)m * N + n0 + tx * 8;
        const float* brow = bias + n0 + tx * 8;
#pragma unroll
        for (int j = 0; j < 8; j++) crow[j] = acc[i][j] + brow[j];
    }
}

// ---------------- banded attention ----------------
// dir = 0 : left  (j in [i-9, i]);  dir = 1 : right (j in [i, i+9])
// one warp per (b, s, h); writes compact (B, S, D)
__global__ void k_band_attn(int dir)
{
    int gwarp = (blockIdx.x * blockDim.x + threadIdx.x) >> 5;
    int lane  = threadIdx.x & 31;
    if (gwarp >= BB * SS * HH) return;

    int h = gwarp % HH;
    int s = (gwarp / HH) % SS;
    int b = gwarp / (HH * SS);
    int i = s + WW;                // global row in padded sequence

    int jlo, jhi;
    if (dir == 0) { jlo = max(i - (WW + 1), 0); jhi = i; }
    else          { jlo = i; jhi = min(i + (WW + 1), SP2 - 1); }

    const float* qr = g_q + ((size_t)b * SP2 + i) * DD + h * DKK;
    float q0 = qr[lane];
    float q1 = qr[lane + 32];

    float sc[10];
#pragma unroll
    for (int t = 0; t < 10; t++) {
        int j = jlo + t;
        int ja = min(j, SP2 - 1);
        const float* kr = g_k + ((size_t)b * SP2 + ja) * DD + h * DKK;
        float p = q0 * kr[lane] + q1 * kr[lane + 32];
#pragma unroll
        for (int o = 16; o > 0; o >>= 1) p += __shfl_xor_sync(0xffffffffu, p, o);
        sc[t] = (j <= jhi) ? p * 0.125f : -1e9f;
    }

    float mx = -1e30f;
#pragma unroll
    for (int t = 0; t < 10; t++) mx = fmaxf(mx, sc[t]);
    float sum = 0.f;
#pragma unroll
    for (int t = 0; t < 10; t++) { sc[t] = __expf(sc[t] - mx); sum += sc[t]; }
    float inv = 1.f / sum;

    float o0 = 0.f, o1 = 0.f;
#pragma unroll
    for (int t = 0; t < 10; t++) {
        int j = jlo + t;
        int ja = min(j, SP2 - 1);
        const float* vr = g_v + ((size_t)b * SP2 + ja) * DD + h * DKK;
        float p = sc[t] * inv;
        o0 = fmaf(p, vr[lane], o0);
        o1 = fmaf(p, vr[lane + 32], o1);
    }

    float* orow = g_attn + ((size_t)b * SS + s) * DD + h * DKK;
    orow[lane]      = o0;
    orow[lane + 32] = o1;
}

// ---------------- add relative sliding-window sum ----------------
// dir = 0 : x += sum_j lw[j] * newin[b, s+j]
// dir = 1 : x += sum_j rw[j] * newin[b, W+s+j]
__global__ void k_addrel(const float* __restrict__ wv, int dir)
{
    int idx = blockIdx.x * blockDim.x + threadIdx.x;   // over B*S*D/4
    int total = BB * SS * (DD / 4);
    if (idx >= total) return;
    int d4 = idx % (DD / 4);
    int s  = (idx / (DD / 4)) % SS;
    int b  = idx / ((DD / 4) * SS);

    int base = (dir == 0) ? s : (s + WW);
    float4* xp = (float4*)(g_x + ((size_t)b * SS + s) * DD) + d4;
    float4 acc = *xp;
#pragma unroll
    for (int j = 0; j <= WW; j++) {
        float w = wv[j];
        float4 nv = ((const float4*)(g_newin + ((size_t)b * SP2 + base + j) * DD))[d4];
        acc.x = fmaf(w, nv.x, acc.x);
        acc.y = fmaf(w, nv.y, acc.y);
        acc.z = fmaf(w, nv.z, acc.z);
        acc.w = fmaf(w, nv.w, acc.w);
    }
    *xp = acc;
}

// ---------------- highway gate: out = g*x + (1-g)*relu(nl) ----------------
__global__ void k_hw_gate(float* __restrict__ out, int outStride, int colOff)
{
    int idx = blockIdx.x * blockDim.x + threadIdx.x;   // over B*S*D
    int total = BB * SS * DD;
    if (idx >= total) return;
    int d = idx % DD;
    int m = idx / DD;

    float nl = fmaxf(g_proj[(size_t)m * DD2 + d], 0.f);
    float gv = g_proj[(size_t)m * DD2 + DD + d];
    float g  = 1.f / (1.f + __expf(-gv));
    float xv = g_x[(size_t)m * DD + d];
    out[(size_t)m * outStride + colOff + d] = g * xv + (1.f - g) * nl;
}

// ---------------- launch ----------------
extern "C" void kernel_launch(void* const* d_in, const int* in_sizes, int n_in,
                              void* d_out, int out_size)
{
    const float* x     = (const float*)d_in[0];
    const float* lW    = (const float*)d_in[1];
    const float* lb    = (const float*)d_in[2];
    const float* rW    = (const float*)d_in[3];
    const float* rb    = (const float*)d_in[4];
    const float* lpad  = (const float*)d_in[5];
    const float* rpad  = (const float*)d_in[6];
    const float* lw    = (const float*)d_in[7];
    const float* rw    = (const float*)d_in[8];
    const float* lhwW  = (const float*)d_in[9];
    const float* lhwb  = (const float*)d_in[10];
    const float* rhwW  = (const float*)d_in[11];
    const float* rhwb  = (const float*)d_in[12];
    float* out = (float*)d_out;

    float *p_newin, *p_q, *p_k, *p_v, *p_attn, *p_x, *p_proj;
    cudaGetSymbolAddress((void**)&p_newin, g_newin);
    cudaGetSymbolAddress((void**)&p_q, g_q);
    cudaGetSymbolAddress((void**)&p_k, g_k);
    cudaGetSymbolAddress((void**)&p_v, g_v);
    cudaGetSymbolAddress((void**)&p_attn, g_attn);
    cudaGetSymbolAddress((void**)&p_x, g_x);
    cudaGetSymbolAddress((void**)&p_proj, g_proj);

    // build padded input
    {
        int total = BB * SP2 * (DD / 4);
        k_build_newin<<<(total + 255) / 256, 256>>>(x, lpad, rpad);
    }

    const int M2 = BB * SP2;   // 8320
    const int M1 = BB * SS;    // 8192

    for (int side = 0; side < 2; side++) {
        const float* aW  = side ? rW : lW;
        const float* ab  = side ? rb : lb;
        const float* hwW = side ? rhwW : lhwW;
        const float* hwb = side ? rhwb : lhwb;
        const float* relw = side ? rw : lw;

        // q, k, v projections over all S2 rows
        dim3 gq(DD / 128, M2 / 128);
        k_sgemm<<<gq, 256>>>(p_newin, aW + 0 * DD * DD, ab + 0 * DD, p_q, M2, DD, DD);
        k_sgemm<<<gq, 256>>>(p_newin, aW + 1 * DD * DD, ab + 1 * DD, p_k, M2, DD, DD);
        k_sgemm<<<gq, 256>>>(p_newin, aW + 2 * DD * DD, ab + 2 * DD, p_v, M2, DD, DD);

        // banded attention (only the S rows that survive the slice)
        {
            int warps = BB * SS * HH;
            k_band_attn<<<(warps * 32 + 255) / 256, 256>>>(side);
        }

        // output projection -> g_x
        dim3 go(DD / 128, M1 / 128);
        k_sgemm<<<go, 256>>>(p_attn, aW + 3 * DD * DD, ab + 3 * DD, p_x, M1, DD, DD);

        // add relative sliding sum
        {
            int total = BB * SS * (DD / 4);
            k_addrel<<<(total + 255) / 256, 256>>>(relw, side);
        }

        // highway layers
        dim3 gh(DD2 / 128, M1 / 128);
        int totalE = BB * SS * DD;
        for (int l = 0; l < 2; l++) {
            k_sgemm<<<gh, 256>>>(p_x, hwW + (size_t)l * DD * DD2, hwb + (size_t)l * DD2,
                                 p_proj, M1, DD2, DD);
            if (l == 0)
                k_hw_gate<<<(totalE + 255) / 256, 256>>>(p_x, DD, 0);
            else
                k_hw_gate<<<(totalE + 255) / 256, 256>>>(out, DD2, side * DD);
        }
    }
}

// round 3
// speedup vs baseline: 2.4608x; 2.4608x over previous
#include <cuda_runtime.h>
#include <cuda_bf16.h>
#include <cstdint>
#include <math.h>

#define BB 8
#define SS 1024
#define DD 512
#define HH 8
#define WW 8
#define DKK 64
#define SP2 1040   // S + 2*WIDTH
#define DD2 1024   // 2*D

// GEMM tiling
#define STAGES 3
#define KCH 16                        // K elements per chunk
#define ROWSTRIDE 20                  // floats per smem row (16 + 4 pad) — conflict-free
#define STAGE_FLOATS (128 * ROWSTRIDE)
#define STAGE_BYTES  (STAGE_FLOATS * 4)
#define SMEM_SZ (2 * STAGES * STAGE_BYTES)   // 61440 B

// ---------------- scratch (static device allocations) ----------------
__device__ float g_newin[(size_t)BB * SP2 * DD];
__device__ float g_q[(size_t)BB * SP2 * DD];
__device__ float g_k[(size_t)BB * SP2 * DD];
__device__ float g_v[(size_t)BB * SP2 * DD];
__device__ float g_attn[(size_t)BB * SS * DD];
__device__ float g_x[(size_t)BB * SS * DD];
__device__ float g_proj[(size_t)BB * SS * DD2];
// transposed weights [N][K] (rounded to tf32)
__device__ float g_lWt[4 * DD * DD];
__device__ float g_rWt[4 * DD * DD];
__device__ float g_lhwWt[2 * DD2 * DD];
__device__ float g_rhwWt[2 * DD2 * DD];

// ---------------- helpers ----------------
__device__ __forceinline__ uint32_t smem_u32(const void* p) {
    uint32_t a;
    asm("{ .reg .u64 t; cvta.to.shared.u64 t, %1; cvt.u32.u64 %0, t; }" : "=r"(a) : "l"(p));
    return a;
}
__device__ __forceinline__ void cpa16(uint32_t dst, const void* src) {
    asm volatile("cp.async.cg.shared.global [%0], [%1], 16;" :: "r"(dst), "l"(src));
}
__device__ __forceinline__ void mma_tf32(float* d, const uint32_t* a, const uint32_t* b) {
    asm volatile(
        "mma.sync.aligned.m16n8k8.row.col.f32.tf32.tf32.f32 "
        "{%0,%1,%2,%3}, {%4,%5,%6,%7}, {%8,%9}, {%0,%1,%2,%3};"
        : "+f"(d[0]), "+f"(d[1]), "+f"(d[2]), "+f"(d[3])
        : "r"(a[0]), "r"(a[1]), "r"(a[2]), "r"(a[3]), "r"(b[0]), "r"(b[1]));
}

// ---------------- mma.sync tf32 GEMM: C[M,N] = A[M,K] @ Bt[N,K]^T + bias ----------------
// CTA tile 128x128, 256 threads = 8 warps in 4(M) x 2(N); warp tile 32x64.
__global__ void __launch_bounds__(256)
k_tgemm(const float* __restrict__ A, const float* __restrict__ Bt,
        const float* __restrict__ bias, float* __restrict__ C,
        int M, int N, int K)
{
    extern __shared__ float smf[];
    float* smA = smf;
    float* smB = smf + STAGES * STAGE_FLOATS;

    const int tid = threadIdx.x;
    const int wid = tid >> 5;
    const int lane = tid & 31;
    const int warp_m = wid & 3;       // 0..3  -> 32 rows each
    const int warp_n = wid >> 2;      // 0..1  -> 64 cols each
    const int m0 = blockIdx.y * 128;
    const int n0 = blockIdx.x * 128;
    const int nch = K / KCH;

    const uint32_t sbA = smem_u32(smA);
    const uint32_t sbB = smem_u32(smB);

    // loader mapping: thread -> (row = tid>>1, k-seg = (tid&1)*8), two 16B cp.async each
    const int ldrow = tid >> 1;
    const int ldseg = (tid & 1) * 8;
    const float* agp = A  + (size_t)(m0 + ldrow) * K + ldseg;
    const float* bgp = Bt + (size_t)(n0 + ldrow) * K + ldseg;
    const uint32_t daBase = sbA + (uint32_t)(ldrow * ROWSTRIDE + ldseg) * 4;
    const uint32_t dbBase = sbB + (uint32_t)(ldrow * ROWSTRIDE + ldseg) * 4;

    float acc[2][8][4];
#pragma unroll
    for (int mi = 0; mi < 2; mi++)
#pragma unroll
        for (int ni = 0; ni < 8; ni++)
#pragma unroll
            for (int j = 0; j < 4; j++) acc[mi][ni][j] = 0.f;

#define ISSUE(c) do {                                                   \
        int _sl = (c) % STAGES;                                         \
        uint32_t _da = daBase + _sl * STAGE_BYTES;                      \
        uint32_t _db = dbBase + _sl * STAGE_BYTES;                      \
        cpa16(_da,      agp + (c) * KCH);                               \
        cpa16(_da + 16, agp + (c) * KCH + 4);                           \
        cpa16(_db,      bgp + (c) * KCH);                               \
        cpa16(_db + 16, bgp + (c) * KCH + 4);                           \
        asm volatile("cp.async.commit_group;" ::: "memory");            \
    } while (0)

    ISSUE(0);
    ISSUE(1);

    for (int c = 0; c < nch; c++) {
        if (c + 2 < nch) { ISSUE(c + 2); }
        else { asm volatile("cp.async.commit_group;" ::: "memory"); }
        asm volatile("cp.async.wait_group 2;" ::: "memory");
        __syncthreads();

        const int sl = c % STAGES;
        const float* As = smA + sl * STAGE_FLOATS;
        const float* Bs = smB + sl * STAGE_FLOATS;

#pragma unroll
        for (int s = 0; s < 2; s++) {
            const int cc = s * 8 + (lane & 3);
            uint32_t afr[2][4];
#pragma unroll
            for (int mi = 0; mi < 2; mi++) {
                const int r = warp_m * 32 + mi * 16 + (lane >> 2);
                afr[mi][0] = __float_as_uint(As[r * ROWSTRIDE + cc]);
                afr[mi][1] = __float_as_uint(As[(r + 8) * ROWSTRIDE + cc]);
                afr[mi][2] = __float_as_uint(As[r * ROWSTRIDE + cc + 4]);
                afr[mi][3] = __float_as_uint(As[(r + 8) * ROWSTRIDE + cc + 4]);
            }
            uint32_t bfr[8][2];
#pragma unroll
            for (int ni = 0; ni < 8; ni++) {
                const int n = warp_n * 64 + ni * 8 + (lane >> 2);
                bfr[ni][0] = __float_as_uint(Bs[n * ROWSTRIDE + cc]);
                bfr[ni][1] = __float_as_uint(Bs[n * ROWSTRIDE + cc + 4]);
            }
#pragma unroll
            for (int mi = 0; mi < 2; mi++)
#pragma unroll
                for (int ni = 0; ni < 8; ni++)
                    mma_tf32(acc[mi][ni], afr[mi], bfr[ni]);
        }
        __syncthreads();
    }
#undef ISSUE

    // epilogue
#pragma unroll
    for (int mi = 0; mi < 2; mi++) {
        const int r = m0 + warp_m * 32 + mi * 16 + (lane >> 2);
#pragma unroll
        for (int ni = 0; ni < 8; ni++) {
            const int n = n0 + warp_n * 64 + ni * 8 + 2 * (lane & 3);
            const float b0 = bias[n], b1 = bias[n + 1];
            float2 v0 = make_float2(acc[mi][ni][0] + b0, acc[mi][ni][1] + b1);
            float2 v1 = make_float2(acc[mi][ni][2] + b0, acc[mi][ni][3] + b1);
            *(float2*)(C + (size_t)r * N + n) = v0;
            *(float2*)(C + (size_t)(r + 8) * N + n) = v1;
        }
    }
}

// ---------------- weight transpose (+ tf32 rounding): out[c][r] = tf32(in[r][c]) ----------------
__global__ void k_transpose(const float* __restrict__ in, float* __restrict__ out,
                            int R, int Ccols)
{
    __shared__ float t[32][33];
    int rb = blockIdx.y * 32, cb = blockIdx.x * 32;
    t[threadIdx.y][threadIdx.x] = in[(size_t)(rb + threadIdx.y) * Ccols + cb + threadIdx.x];
    __syncthreads();
    float v = t[threadIdx.x][threadIdx.y];
    uint32_t r;
    asm("cvt.rna.tf32.f32 %0, %1;" : "=r"(r) : "f"(v));
    out[(size_t)(cb + threadIdx.y) * R + rb + threadIdx.x] = __uint_as_float(r);
}

// ---------------- build padded input ----------------
__global__ void k_build_newin(const float* __restrict__ x,
                              const float* __restrict__ lpad,
                              const float* __restrict__ rpad)
{
    int idx = blockIdx.x * blockDim.x + threadIdx.x;
    int total = BB * SP2 * (DD / 4);
    if (idx >= total) return;
    int d4 = idx % (DD / 4);
    int s  = (idx / (DD / 4)) % SP2;
    int b  = idx / ((DD / 4) * SP2);

    float4 v;
    if (s < WW) {
        v = ((const float4*)(lpad + (size_t)s * DD))[d4];
    } else if (s < WW + SS) {
        v = ((const float4*)(x + ((size_t)b * SS + (s - WW)) * DD))[d4];
    } else {
        v = ((const float4*)(rpad + (size_t)(s - WW - SS) * DD))[d4];
    }
    ((float4*)(g_newin + ((size_t)b * SP2 + s) * DD))[d4] = v;
}

// ---------------- banded attention ----------------
__global__ void k_band_attn(int dir)
{
    int gwarp = (blockIdx.x * blockDim.x + threadIdx.x) >> 5;
    int lane  = threadIdx.x & 31;
    if (gwarp >= BB * SS * HH) return;

    int h = gwarp % HH;
    int s = (gwarp / HH) % SS;
    int b = gwarp / (HH * SS);
    int i = s + WW;

    int jlo, jhi;
    if (dir == 0) { jlo = max(i - (WW + 1), 0); jhi = i; }
    else          { jlo = i; jhi = min(i + (WW + 1), SP2 - 1); }

    const float* qr = g_q + ((size_t)b * SP2 + i) * DD + h * DKK;
    float q0 = qr[lane];
    float q1 = qr[lane + 32];

    float sc[10];
#pragma unroll
    for (int t = 0; t < 10; t++) {
        int j = jlo + t;
        int ja = min(j, SP2 - 1);
        const float* kr = g_k + ((size_t)b * SP2 + ja) * DD + h * DKK;
        float p = q0 * kr[lane] + q1 * kr[lane + 32];
#pragma unroll
        for (int o = 16; o > 0; o >>= 1) p += __shfl_xor_sync(0xffffffffu, p, o);
        sc[t] = (j <= jhi) ? p * 0.125f : -1e9f;
    }

    float mx = -1e30f;
#pragma unroll
    for (int t = 0; t < 10; t++) mx = fmaxf(mx, sc[t]);
    float sum = 0.f;
#pragma unroll
    for (int t = 0; t < 10; t++) { sc[t] = __expf(sc[t] - mx); sum += sc[t]; }
    float inv = 1.f / sum;

    float o0 = 0.f, o1 = 0.f;
#pragma unroll
    for (int t = 0; t < 10; t++) {
        int j = jlo + t;
        int ja = min(j, SP2 - 1);
        const float* vr = g_v + ((size_t)b * SP2 + ja) * DD + h * DKK;
        float p = sc[t] * inv;
        o0 = fmaf(p, vr[lane], o0);
        o1 = fmaf(p, vr[lane + 32], o1);
    }

    float* orow = g_attn + ((size_t)b * SS + s) * DD + h * DKK;
    orow[lane]      = o0;
    orow[lane + 32] = o1;
}

// ---------------- add relative sliding-window sum ----------------
__global__ void k_addrel(const float* __restrict__ wv, int dir)
{
    int idx = blockIdx.x * blockDim.x + threadIdx.x;
    int total = BB * SS * (DD / 4);
    if (idx >= total) return;
    int d4 = idx % (DD / 4);
    int s  = (idx / (DD / 4)) % SS;
    int b  = idx / ((DD / 4) * SS);

    int base = (dir == 0) ? s : (s + WW);
    float4* xp = (float4*)(g_x + ((size_t)b * SS + s) * DD) + d4;
    float4 acc = *xp;
#pragma unroll
    for (int j = 0; j <= WW; j++) {
        float w = wv[j];
        float4 nv = ((const float4*)(g_newin + ((size_t)b * SP2 + base + j) * DD))[d4];
        acc.x = fmaf(w, nv.x, acc.x);
        acc.y = fmaf(w, nv.y, acc.y);
        acc.z = fmaf(w, nv.z, acc.z);
        acc.w = fmaf(w, nv.w, acc.w);
    }
    *xp = acc;
}

// ---------------- highway gate ----------------
__global__ void k_hw_gate(float* __restrict__ out, int outStride, int colOff)
{
    int idx = blockIdx.x * blockDim.x + threadIdx.x;
    int total = BB * SS * DD;
    if (idx >= total) return;
    int d = idx % DD;
    int m = idx / DD;

    float nl = fmaxf(g_proj[(size_t)m * DD2 + d], 0.f);
    float gv = g_proj[(size_t)m * DD2 + DD + d];
    float g  = 1.f / (1.f + __expf(-gv));
    float xv = g_x[(size_t)m * DD + d];
    out[(size_t)m * outStride + colOff + d] = g * xv + (1.f - g) * nl;
}

// ---------------- launch ----------------
extern "C" void kernel_launch(void* const* d_in, const int* in_sizes, int n_in,
                              void* d_out, int out_size)
{
    const float* x     = (const float*)d_in[0];
    const float* lW    = (const float*)d_in[1];
    const float* lb    = (const float*)d_in[2];
    const float* rW    = (const float*)d_in[3];
    const float* rb    = (const float*)d_in[4];
    const float* lpad  = (const float*)d_in[5];
    const float* rpad  = (const float*)d_in[6];
    const float* lw    = (const float*)d_in[7];
    const float* rw    = (const float*)d_in[8];
    const float* lhwW  = (const float*)d_in[9];
    const float* lhwb  = (const float*)d_in[10];
    const float* rhwW  = (const float*)d_in[11];
    const float* rhwb  = (const float*)d_in[12];
    float* out = (float*)d_out;

    static bool attr_set = false;
    if (!attr_set) {
        cudaFuncSetAttribute(k_tgemm, cudaFuncAttributeMaxDynamicSharedMemorySize, SMEM_SZ);
        attr_set = true;
    }

    float *p_newin, *p_q, *p_k, *p_v, *p_attn, *p_x, *p_proj;
    float *p_lWt, *p_rWt, *p_lhwWt, *p_rhwWt;
    cudaGetSymbolAddress((void**)&p_newin, g_newin);
    cudaGetSymbolAddress((void**)&p_q, g_q);
    cudaGetSymbolAddress((void**)&p_k, g_k);
    cudaGetSymbolAddress((void**)&p_v, g_v);
    cudaGetSymbolAddress((void**)&p_attn, g_attn);
    cudaGetSymbolAddress((void**)&p_x, g_x);
    cudaGetSymbolAddress((void**)&p_proj, g_proj);
    cudaGetSymbolAddress((void**)&p_lWt, g_lWt);
    cudaGetSymbolAddress((void**)&p_rWt, g_rWt);
    cudaGetSymbolAddress((void**)&p_lhwWt, g_lhwWt);
    cudaGetSymbolAddress((void**)&p_rhwWt, g_rhwWt);

    // weight transposes (+ tf32 rounding of weights)
    {
        dim3 blk(32, 32);
        dim3 gsq(DD / 32, DD / 32);
        for (int i = 0; i < 4; i++) {
            k_transpose<<<gsq, blk>>>(lW + (size_t)i * DD * DD, p_lWt + (size_t)i * DD * DD, DD, DD);
            k_transpose<<<gsq, blk>>>(rW + (size_t)i * DD * DD, p_rWt + (size_t)i * DD * DD, DD, DD);
        }
        dim3 ghw(DD2 / 32, DD / 32);
        for (int l = 0; l < 2; l++) {
            k_transpose<<<ghw, blk>>>(lhwW + (size_t)l * DD * DD2, p_lhwWt + (size_t)l * DD2 * DD, DD, DD2);
            k_transpose<<<ghw, blk>>>(rhwW + (size_t)l * DD * DD2, p_rhwWt + (size_t)l * DD2 * DD, DD, DD2);
        }
    }

    // build padded input
    {
        int total = BB * SP2 * (DD / 4);
        k_build_newin<<<(total + 255) / 256, 256>>>(x, lpad, rpad);
    }

    const int M2 = BB * SP2;   // 8320
    const int M1 = BB * SS;    // 8192

    for (int side = 0; side < 2; side++) {
        const float* aWt = side ? p_rWt : p_lWt;
        const float* ab  = side ? rb : lb;
        const float* hwWt = side ? p_rhwWt : p_lhwWt;
        const float* hwb  = side ? rhwb : lhwb;
        const float* relw = side ? rw : lw;

        // q, k, v projections over all S2 rows
        dim3 gq(DD / 128, M2 / 128);
        k_tgemm<<<gq, 256, SMEM_SZ>>>(p_newin, aWt + 0 * DD * DD, ab + 0 * DD, p_q, M2, DD, DD);
        k_tgemm<<<gq, 256, SMEM_SZ>>>(p_newin, aWt + 1 * DD * DD, ab + 1 * DD, p_k, M2, DD, DD);
        k_tgemm<<<gq, 256, SMEM_SZ>>>(p_newin, aWt + 2 * DD * DD, ab + 2 * DD, p_v, M2, DD, DD);

        // banded attention
        {
            int warps = BB * SS * HH;
            k_band_attn<<<(warps * 32 + 255) / 256, 256>>>(side);
        }

        // output projection -> g_x
        dim3 go(DD / 128, M1 / 128);
        k_tgemm<<<go, 256, SMEM_SZ>>>(p_attn, aWt + 3 * DD * DD, ab + 3 * DD, p_x, M1, DD, DD);

        // add relative sliding sum
        {
            int total = BB * SS * (DD / 4);
            k_addrel<<<(total + 255) / 256, 256>>>(relw, side);
        }

        // highway layers
        dim3 gh(DD2 / 128, M1 / 128);
        int totalE = BB * SS * DD;
        for (int l = 0; l < 2; l++) {
            k_tgemm<<<gh, 256, SMEM_SZ>>>(p_x, hwWt + (size_t)l * DD2 * DD, hwb + (size_t)l * DD2,
                                          p_proj, M1, DD2, DD);
            if (l == 0)
                k_hw_gate<<<(totalE + 255) / 256, 256>>>(p_x, DD, 0);
            else
                k_hw_gate<<<(totalE + 255) / 256, 256>>>(out, DD2, side * DD);
        }
    }
}

// round 4
// speedup vs baseline: 2.5788x; 1.0480x over previous
#include <cuda_runtime.h>
#include <cuda_bf16.h>
#include <cstdint>
#include <math.h>

#define BB 8
#define SS 1024
#define DD 512
#define HH 8
#define WW 8
#define DKK 64
#define SP2 1040   // S + 2*WIDTH
#define DD2 1024   // 2*D

// GEMM tiling
#define STAGES 3
#define KCH 16
#define ROWSTRIDE 20
#define STAGE_FLOATS (128 * ROWSTRIDE)
#define STAGE_BYTES  (STAGE_FLOATS * 4)
#define SMEM_SZ (2 * STAGES * STAGE_BYTES)   // 61440 B

// ---------------- scratch ----------------
__device__ float g_newin[(size_t)BB * SP2 * DD];
__device__ float g_qkv[(size_t)BB * SP2 * 3072];       // both sides: [row][side*1536 + {q,k,v}*512 + d]
__device__ float g_attn[2 * (size_t)BB * SS * DD];
__device__ float g_x[(size_t)BB * SS * DD];
__device__ float g_xb[(size_t)BB * SS * DD];
// transposed weights [N][K], tf32-rounded
__device__ float g_qkvWt[2 * 3 * DD * DD];             // [side*1536 + i*512 + n][k]
__device__ float g_opWt[2 * DD * DD];
__device__ float g_hwWt[2 * 2 * DD2 * DD];             // [(side*2+l)*1024 + n][k]
__device__ float g_qkvb[2 * 3 * DD];

// ---------------- helpers ----------------
__device__ __forceinline__ uint32_t smem_u32(const void* p) {
    uint32_t a;
    asm("{ .reg .u64 t; cvta.to.shared.u64 t, %1; cvt.u32.u64 %0, t; }" : "=r"(a) : "l"(p));
    return a;
}
__device__ __forceinline__ void cpa16(uint32_t dst, const void* src) {
    asm volatile("cp.async.cg.shared.global [%0], [%1], 16;" :: "r"(dst), "l"(src));
}
__device__ __forceinline__ void mma_tf32(float* d, const uint32_t* a, const uint32_t* b) {
    asm volatile(
        "mma.sync.aligned.m16n8k8.row.col.f32.tf32.tf32.f32 "
        "{%0,%1,%2,%3}, {%4,%5,%6,%7}, {%8,%9}, {%0,%1,%2,%3};"
        : "+f"(d[0]), "+f"(d[1]), "+f"(d[2]), "+f"(d[3])
        : "r"(a[0]), "r"(a[1]), "r"(a[2]), "r"(a[3]), "r"(b[0]), "r"(b[1]));
}

#define GEMM_PRE()                                                        \
    extern __shared__ float smf[];                                        \
    float* smA = smf;                                                     \
    float* smB = smf + STAGES * STAGE_FLOATS;                             \
    const int tid = threadIdx.x;                                          \
    const int wid = tid >> 5;                                             \
    const int lane = tid & 31;                                            \
    const int warp_m = wid & 3;                                           \
    const int warp_n = wid >> 2;                                          \
    const int m0 = blockIdx.y * 128;                                      \
    const int n0 = blockIdx.x * 128;                                      \
    const uint32_t sbA = smem_u32(smA);                                   \
    const uint32_t sbB = smem_u32(smB);                                   \
    const int ldrow = tid >> 1;                                           \
    const int ldseg = (tid & 1) * 8;                                      \
    const uint32_t daBase = sbA + (uint32_t)(ldrow * ROWSTRIDE + ldseg) * 4; \
    const uint32_t dbBase = sbB + (uint32_t)(ldrow * ROWSTRIDE + ldseg) * 4;

#define ISSUE(c) do {                                                   \
        int _sl = (c) % STAGES;                                         \
        uint32_t _da = daBase + _sl * STAGE_BYTES;                      \
        uint32_t _db = dbBase + _sl * STAGE_BYTES;                      \
        cpa16(_da,      agp + (c) * KCH);                               \
        cpa16(_da + 16, agp + (c) * KCH + 4);                           \
        cpa16(_db,      bgp + (c) * KCH);                               \
        cpa16(_db + 16, bgp + (c) * KCH + 4);                           \
        asm volatile("cp.async.commit_group;" ::: "memory");            \
    } while (0)

// ============ GEMM 1: generic C = A @ Bt^T + bias (128x128 tile) ============
__global__ void __launch_bounds__(256)
k_tgemm(const float* __restrict__ A, const float* __restrict__ Bt,
        const float* __restrict__ bias, float* __restrict__ C,
        int M, int N, int K)
{
    GEMM_PRE();
    const int nch = K / KCH;
    const float* agp = A  + (size_t)(m0 + ldrow) * K + ldseg;
    const float* bgp = Bt + (size_t)(n0 + ldrow) * K + ldseg;

    float acc[2][8][4];
#pragma unroll
    for (int mi = 0; mi < 2; mi++)
#pragma unroll
        for (int ni = 0; ni < 8; ni++)
#pragma unroll
            for (int j = 0; j < 4; j++) acc[mi][ni][j] = 0.f;

    ISSUE(0);
    ISSUE(1);
    for (int c = 0; c < nch; c++) {
        if (c + 2 < nch) { ISSUE(c + 2); }
        else { asm volatile("cp.async.commit_group;" ::: "memory"); }
        asm volatile("cp.async.wait_group 2;" ::: "memory");
        __syncthreads();
        const int sl = c % STAGES;
        const float* As = smA + sl * STAGE_FLOATS;
        const float* Bs = smB + sl * STAGE_FLOATS;
#pragma unroll
        for (int s = 0; s < 2; s++) {
            const int cc = s * 8 + (lane & 3);
            uint32_t afr[2][4];
#pragma unroll
            for (int mi = 0; mi < 2; mi++) {
                const int r = warp_m * 32 + mi * 16 + (lane >> 2);
                afr[mi][0] = __float_as_uint(As[r * ROWSTRIDE + cc]);
                afr[mi][1] = __float_as_uint(As[(r + 8) * ROWSTRIDE + cc]);
                afr[mi][2] = __float_as_uint(As[r * ROWSTRIDE + cc + 4]);
                afr[mi][3] = __float_as_uint(As[(r + 8) * ROWSTRIDE + cc + 4]);
            }
            uint32_t bfr[8][2];
#pragma unroll
            for (int ni = 0; ni < 8; ni++) {
                const int n = warp_n * 64 + ni * 8 + (lane >> 2);
                bfr[ni][0] = __float_as_uint(Bs[n * ROWSTRIDE + cc]);
                bfr[ni][1] = __float_as_uint(Bs[n * ROWSTRIDE + cc + 4]);
            }
#pragma unroll
            for (int mi = 0; mi < 2; mi++)
#pragma unroll
                for (int ni = 0; ni < 8; ni++)
                    mma_tf32(acc[mi][ni], afr[mi], bfr[ni]);
        }
        __syncthreads();
    }

#pragma unroll
    for (int mi = 0; mi < 2; mi++) {
        const int r = m0 + warp_m * 32 + mi * 16 + (lane >> 2);
#pragma unroll
        for (int ni = 0; ni < 8; ni++) {
            const int n = n0 + warp_n * 64 + ni * 8 + 2 * (lane & 3);
            const float b0 = bias[n], b1 = bias[n + 1];
            *(float2*)(C + (size_t)r * N + n) = make_float2(acc[mi][ni][0] + b0, acc[mi][ni][1] + b1);
            *(float2*)(C + (size_t)(r + 8) * N + n) = make_float2(acc[mi][ni][2] + b0, acc[mi][ni][3] + b1);
        }
    }
}

// ============ GEMM 2: out-proj with fused relative-window add ============
// C[m][n] = (A @ Bt^T)[m][n] + bias[n] + sum_j w[j] * newin[b, base(m)+j, n]
__global__ void __launch_bounds__(256)
k_opgemm(const float* __restrict__ A, const float* __restrict__ Bt,
         const float* __restrict__ bias, float* __restrict__ C,
         const float* __restrict__ relw, int dir, int M, int N, int K)
{
    GEMM_PRE();
    const int nch = K / KCH;
    const float* agp = A  + (size_t)(m0 + ldrow) * K + ldseg;
    const float* bgp = Bt + (size_t)(n0 + ldrow) * K + ldseg;

    float acc[2][8][4];
#pragma unroll
    for (int mi = 0; mi < 2; mi++)
#pragma unroll
        for (int ni = 0; ni < 8; ni++)
#pragma unroll
            for (int j = 0; j < 4; j++) acc[mi][ni][j] = 0.f;

    ISSUE(0);
    ISSUE(1);
    for (int c = 0; c < nch; c++) {
        if (c + 2 < nch) { ISSUE(c + 2); }
        else { asm volatile("cp.async.commit_group;" ::: "memory"); }
        asm volatile("cp.async.wait_group 2;" ::: "memory");
        __syncthreads();
        const int sl = c % STAGES;
        const float* As = smA + sl * STAGE_FLOATS;
        const float* Bs = smB + sl * STAGE_FLOATS;
#pragma unroll
        for (int s = 0; s < 2; s++) {
            const int cc = s * 8 + (lane & 3);
            uint32_t afr[2][4];
#pragma unroll
            for (int mi = 0; mi < 2; mi++) {
                const int r = warp_m * 32 + mi * 16 + (lane >> 2);
                afr[mi][0] = __float_as_uint(As[r * ROWSTRIDE + cc]);
                afr[mi][1] = __float_as_uint(As[(r + 8) * ROWSTRIDE + cc]);
                afr[mi][2] = __float_as_uint(As[r * ROWSTRIDE + cc + 4]);
                afr[mi][3] = __float_as_uint(As[(r + 8) * ROWSTRIDE + cc + 4]);
            }
            uint32_t bfr[8][2];
#pragma unroll
            for (int ni = 0; ni < 8; ni++) {
                const int n = warp_n * 64 + ni * 8 + (lane >> 2);
                bfr[ni][0] = __float_as_uint(Bs[n * ROWSTRIDE + cc]);
                bfr[ni][1] = __float_as_uint(Bs[n * ROWSTRIDE + cc + 4]);
            }
#pragma unroll
            for (int mi = 0; mi < 2; mi++)
#pragma unroll
                for (int ni = 0; ni < 8; ni++)
                    mma_tf32(acc[mi][ni], afr[mi], bfr[ni]);
        }
        __syncthreads();
    }

    float wv[WW + 1];
#pragma unroll
    for (int j = 0; j <= WW; j++) wv[j] = relw[j];

#pragma unroll
    for (int mi = 0; mi < 2; mi++) {
#pragma unroll
        for (int half = 0; half < 2; half++) {
            const int r = m0 + warp_m * 32 + mi * 16 + (lane >> 2) + half * 8;
            const int b = r >> 10;
            const int s = r & 1023;
            const int base = (dir == 0) ? s : (s + WW);
            const float* nrow = g_newin + ((size_t)b * SP2 + base) * DD;
#pragma unroll
            for (int ni = 0; ni < 8; ni++) {
                const int n = n0 + warp_n * 64 + ni * 8 + 2 * (lane & 3);
                float v0 = acc[mi][ni][half * 2 + 0] + bias[n];
                float v1 = acc[mi][ni][half * 2 + 1] + bias[n + 1];
#pragma unroll
                for (int j = 0; j <= WW; j++) {
                    float2 nv = *(const float2*)(nrow + (size_t)j * DD + n);
                    v0 = fmaf(wv[j], nv.x, v0);
                    v1 = fmaf(wv[j], nv.y, v1);
                }
                *(float2*)(C + (size_t)r * N + n) = make_float2(v0, v1);
            }
        }
    }
}

// ============ GEMM 3: highway layer with fused gate ============
// proj_nl = A @ Bt[0:512]^T + b[0:512]; proj_g = A @ Bt[512:1024]^T + b[512:1024]
// dest[m][colOff+n] = sig(proj_g) * Xold[m][n] + (1-sig)*relu(proj_nl)
// CTA tile: 128 rows x 64 cols (per half). 8 warps: 4(M) x 2(N=32 each).
__global__ void __launch_bounds__(256)
k_hwgemm(const float* __restrict__ A, const float* __restrict__ Bt,
         const float* __restrict__ bias, const float* __restrict__ Xold,
         float* __restrict__ dest, int destStride, int colOff, int K)
{
    extern __shared__ float smf[];
    float* smA = smf;
    float* smB = smf + STAGES * STAGE_FLOATS;
    const int tid = threadIdx.x;
    const int wid = tid >> 5;
    const int lane = tid & 31;
    const int warp_m = wid & 3;
    const int warp_n = wid >> 2;
    const int m0 = blockIdx.y * 128;
    const int n0 = blockIdx.x * 64;
    const uint32_t sbA = smem_u32(smA);
    const uint32_t sbB = smem_u32(smB);
    const int ldrow = tid >> 1;
    const int ldseg = (tid & 1) * 8;
    const uint32_t daBase = sbA + (uint32_t)(ldrow * ROWSTRIDE + ldseg) * 4;
    const uint32_t dbBase = sbB + (uint32_t)(ldrow * ROWSTRIDE + ldseg) * 4;
    const int nch = K / KCH;

    const float* agp = A + (size_t)(m0 + ldrow) * K + ldseg;
    const int brow_g = (ldrow < 64) ? (n0 + ldrow) : (512 + n0 + ldrow - 64);
    const float* bgp = Bt + (size_t)brow_g * K + ldseg;

    float accN[2][4][4], accG[2][4][4];
#pragma unroll
    for (int mi = 0; mi < 2; mi++)
#pragma unroll
        for (int ni = 0; ni < 4; ni++)
#pragma unroll
            for (int j = 0; j < 4; j++) { accN[mi][ni][j] = 0.f; accG[mi][ni][j] = 0.f; }

    ISSUE(0);
    ISSUE(1);
    for (int c = 0; c < nch; c++) {
        if (c + 2 < nch) { ISSUE(c + 2); }
        else { asm volatile("cp.async.commit_group;" ::: "memory"); }
        asm volatile("cp.async.wait_group 2;" ::: "memory");
        __syncthreads();
        const int sl = c % STAGES;
        const float* As = smA + sl * STAGE_FLOATS;
        const float* Bs = smB + sl * STAGE_FLOATS;
#pragma unroll
        for (int s = 0; s < 2; s++) {
            const int cc = s * 8 + (lane & 3);
            uint32_t afr[2][4];
#pragma unroll
            for (int mi = 0; mi < 2; mi++) {
                const int r = warp_m * 32 + mi * 16 + (lane >> 2);
                afr[mi][0] = __float_as_uint(As[r * ROWSTRIDE + cc]);
                afr[mi][1] = __float_as_uint(As[(r + 8) * ROWSTRIDE + cc]);
                afr[mi][2] = __float_as_uint(As[r * ROWSTRIDE + cc + 4]);
                afr[mi][3] = __float_as_uint(As[(r + 8) * ROWSTRIDE + cc + 4]);
            }
            uint32_t bfrN[4][2], bfrG[4][2];
#pragma unroll
            for (int ni = 0; ni < 4; ni++) {
                const int bn = warp_n * 32 + ni * 8 + (lane >> 2);
                bfrN[ni][0] = __float_as_uint(Bs[bn * ROWSTRIDE + cc]);
                bfrN[ni][1] = __float_as_uint(Bs[bn * ROWSTRIDE + cc + 4]);
                bfrG[ni][0] = __float_as_uint(Bs[(64 + bn) * ROWSTRIDE + cc]);
                bfrG[ni][1] = __float_as_uint(Bs[(64 + bn) * ROWSTRIDE + cc + 4]);
            }
#pragma unroll
            for (int mi = 0; mi < 2; mi++)
#pragma unroll
                for (int ni = 0; ni < 4; ni++) {
                    mma_tf32(accN[mi][ni], afr[mi], bfrN[ni]);
                    mma_tf32(accG[mi][ni], afr[mi], bfrG[ni]);
                }
        }
        __syncthreads();
    }

#pragma unroll
    for (int mi = 0; mi < 2; mi++) {
#pragma unroll
        for (int half = 0; half < 2; half++) {
            const int r = m0 + warp_m * 32 + mi * 16 + (lane >> 2) + half * 8;
#pragma unroll
            for (int ni = 0; ni < 4; ni++) {
                const int n = n0 + warp_n * 32 + ni * 8 + 2 * (lane & 3);
                float nl0 = fmaxf(accN[mi][ni][half * 2 + 0] + bias[n], 0.f);
                float nl1 = fmaxf(accN[mi][ni][half * 2 + 1] + bias[n + 1], 0.f);
                float gv0 = accG[mi][ni][half * 2 + 0] + bias[512 + n];
                float gv1 = accG[mi][ni][half * 2 + 1] + bias[512 + n + 1];
                float g0 = 1.f / (1.f + __expf(-gv0));
                float g1 = 1.f / (1.f + __expf(-gv1));
                float2 xv = *(const float2*)(Xold + (size_t)r * DD + n);
                float o0 = g0 * xv.x + (1.f - g0) * nl0;
                float o1 = g1 * xv.y + (1.f - g1) * nl1;
                *(float2*)(dest + (size_t)r * destStride + colOff + n) = make_float2(o0, o1);
            }
        }
    }
}
#undef ISSUE

// ---------------- transposes (tf32-round weights) ----------------
// attn weights: z -> side = z>>2, i = z&3.  i<3 -> qkvWt rows side*1536+i*512; i==3 -> opWt
__global__ void k_transpose_attn(const float* __restrict__ lW, const float* __restrict__ rW)
{
    __shared__ float t[32][33];
    int z = blockIdx.z;
    int side = z >> 2, i = z & 3;
    const float* in = (side ? rW : lW) + (size_t)i * DD * DD;
    float* outb = (i < 3) ? (g_qkvWt + (size_t)(side * 1536 + i * 512) * DD)
                          : (g_opWt + (size_t)side * DD * DD);
    int rb = blockIdx.y * 32, cb = blockIdx.x * 32;
    t[threadIdx.y][threadIdx.x] = in[(size_t)(rb + threadIdx.y) * DD + cb + threadIdx.x];
    __syncthreads();
    float v = t[threadIdx.x][threadIdx.y];
    uint32_t r;
    asm("cvt.rna.tf32.f32 %0, %1;" : "=r"(r) : "f"(v));
    outb[(size_t)(cb + threadIdx.y) * DD + rb + threadIdx.x] = __uint_as_float(r);
}
// hw weights: z -> side = z>>1, l = z&1. in [512][1024] -> out [(side*2+l)*1024 + n][k]
__global__ void k_transpose_hw(const float* __restrict__ lhwW, const float* __restrict__ rhwW)
{
    __shared__ float t[32][33];
    int z = blockIdx.z;
    int side = z >> 1, l = z & 1;
    const float* in = (side ? rhwW : lhwW) + (size_t)l * DD * DD2;
    float* outb = g_hwWt + (size_t)(side * 2 + l) * DD2 * DD;
    int rb = blockIdx.y * 32, cb = blockIdx.x * 32;
    t[threadIdx.y][threadIdx.x] = in[(size_t)(rb + threadIdx.y) * DD2 + cb + threadIdx.x];
    __syncthreads();
    float v = t[threadIdx.x][threadIdx.y];
    uint32_t r;
    asm("cvt.rna.tf32.f32 %0, %1;" : "=r"(r) : "f"(v));
    outb[(size_t)(cb + threadIdx.y) * DD + rb + threadIdx.x] = __uint_as_float(r);
}
__global__ void k_pack_bias(const float* __restrict__ lb, const float* __restrict__ rb)
{
    int idx = blockIdx.x * blockDim.x + threadIdx.x;   // 0..3071
    if (idx >= 2 * 3 * DD) return;
    int side = idx / 1536;
    int rem = idx % 1536;
    g_qkvb[idx] = (side ? rb : lb)[rem];
}

// ---------------- build padded input ----------------
__global__ void k_build_newin(const float* __restrict__ x,
                              const float* __restrict__ lpad,
                              const float* __restrict__ rpad)
{
    int idx = blockIdx.x * blockDim.x + threadIdx.x;
    int total = BB * SP2 * (DD / 4);
    if (idx >= total) return;
    int d4 = idx % (DD / 4);
    int s  = (idx / (DD / 4)) % SP2;
    int b  = idx / ((DD / 4) * SP2);

    float4 v;
    if (s < WW) {
        v = ((const float4*)(lpad + (size_t)s * DD))[d4];
    } else if (s < WW + SS) {
        v = ((const float4*)(x + ((size_t)b * SS + (s - WW)) * DD))[d4];
    } else {
        v = ((const float4*)(rpad + (size_t)(s - WW - SS) * DD))[d4];
    }
    ((float4*)(g_newin + ((size_t)b * SP2 + s) * DD))[d4] = v;
}

// ---------------- banded attention (both sides) ----------------
__global__ void k_band_attn()
{
    int gwarp = (blockIdx.x * blockDim.x + threadIdx.x) >> 5;
    int lane  = threadIdx.x & 31;
    if (gwarp >= 2 * BB * SS * HH) return;

    int h = gwarp % HH;
    int s = (gwarp / HH) % SS;
    int b = (gwarp / (HH * SS)) % BB;
    int side = gwarp / (HH * SS * BB);
    int i = s + WW;

    int jlo, jhi;
    if (side == 0) { jlo = max(i - (WW + 1), 0); jhi = i; }
    else           { jlo = i; jhi = min(i + (WW + 1), SP2 - 1); }

    const size_t qkvOff = (size_t)side * 1536 + (size_t)h * DKK;
    const float* qr = g_qkv + ((size_t)b * SP2 + i) * 3072 + qkvOff;
    float q0 = qr[lane];
    float q1 = qr[lane + 32];

    float sc[10];
#pragma unroll
    for (int t = 0; t < 10; t++) {
        int j = jlo + t;
        int ja = min(j, SP2 - 1);
        const float* kr = g_qkv + ((size_t)b * SP2 + ja) * 3072 + qkvOff + 512;
        float p = q0 * kr[lane] + q1 * kr[lane + 32];
#pragma unroll
        for (int o = 16; o > 0; o >>= 1) p += __shfl_xor_sync(0xffffffffu, p, o);
        sc[t] = (j <= jhi) ? p * 0.125f : -1e9f;
    }

    float mx = -1e30f;
#pragma unroll
    for (int t = 0; t < 10; t++) mx = fmaxf(mx, sc[t]);
    float sum = 0.f;
#pragma unroll
    for (int t = 0; t < 10; t++) { sc[t] = __expf(sc[t] - mx); sum += sc[t]; }
    float inv = 1.f / sum;

    float o0 = 0.f, o1 = 0.f;
#pragma unroll
    for (int t = 0; t < 10; t++) {
        int j = jlo + t;
        int ja = min(j, SP2 - 1);
        const float* vr = g_qkv + ((size_t)b * SP2 + ja) * 3072 + qkvOff + 1024;
        float p = sc[t] * inv;
        o0 = fmaf(p, vr[lane], o0);
        o1 = fmaf(p, vr[lane + 32], o1);
    }

    float* orow = g_attn + (size_t)side * BB * SS * DD + ((size_t)b * SS + s) * DD + h * DKK;
    orow[lane]      = o0;
    orow[lane + 32] = o1;
}

// ---------------- launch ----------------
extern "C" void kernel_launch(void* const* d_in, const int* in_sizes, int n_in,
                              void* d_out, int out_size)
{
    const float* x     = (const float*)d_in[0];
    const float* lW    = (const float*)d_in[1];
    const float* lb    = (const float*)d_in[2];
    const float* rW    = (const float*)d_in[3];
    const float* rb    = (const float*)d_in[4];
    const float* lpad  = (const float*)d_in[5];
    const float* rpad  = (const float*)d_in[6];
    const float* lw    = (const float*)d_in[7];
    const float* rw    = (const float*)d_in[8];
    const float* lhwW  = (const float*)d_in[9];
    const float* lhwb  = (const float*)d_in[10];
    const float* rhwW  = (const float*)d_in[11];
    const float* rhwb  = (const float*)d_in[12];
    float* out = (float*)d_out;

    static bool attr_set = false;
    if (!attr_set) {
        cudaFuncSetAttribute(k_tgemm, cudaFuncAttributeMaxDynamicSharedMemorySize, SMEM_SZ);
        cudaFuncSetAttribute(k_opgemm, cudaFuncAttributeMaxDynamicSharedMemorySize, SMEM_SZ);
        cudaFuncSetAttribute(k_hwgemm, cudaFuncAttributeMaxDynamicSharedMemorySize, SMEM_SZ);
        attr_set = true;
    }

    float *p_newin, *p_qkv, *p_attn, *p_x, *p_xb;
    float *p_qkvWt, *p_opWt, *p_hwWt, *p_qkvb;
    cudaGetSymbolAddress((void**)&p_newin, g_newin);
    cudaGetSymbolAddress((void**)&p_qkv, g_qkv);
    cudaGetSymbolAddress((void**)&p_attn, g_attn);
    cudaGetSymbolAddress((void**)&p_x, g_x);
    cudaGetSymbolAddress((void**)&p_xb, g_xb);
    cudaGetSymbolAddress((void**)&p_qkvWt, g_qkvWt);
    cudaGetSymbolAddress((void**)&p_opWt, g_opWt);
    cudaGetSymbolAddress((void**)&p_hwWt, g_hwWt);
    cudaGetSymbolAddress((void**)&p_qkvb, g_qkvb);

    // weight prep: 3 launches
    {
        dim3 blk(32, 32);
        k_transpose_attn<<<dim3(16, 16, 8), blk>>>(lW, rW);
        k_transpose_hw<<<dim3(32, 16, 4), blk>>>(lhwW, rhwW);
        k_pack_bias<<<(3072 + 255) / 256, 256>>>(lb, rb);
    }

    // padded input
    {
        int total = BB * SP2 * (DD / 4);
        k_build_newin<<<(total + 255) / 256, 256>>>(x, lpad, rpad);
    }

    const int M2 = BB * SP2;   // 8320
    const int M1 = BB * SS;    // 8192

    // combined QKV for both sides: M2 x 3072
    k_tgemm<<<dim3(3072 / 128, M2 / 128), 256, SMEM_SZ>>>(p_newin, p_qkvWt, p_qkvb, p_qkv,
                                                          M2, 3072, DD);
    // banded attention, both sides
    {
        int warps = 2 * BB * SS * HH;
        k_band_attn<<<(warps * 32 + 255) / 256, 256>>>();
    }

    for (int side = 0; side < 2; side++) {
        const float* ab3  = (side ? rb : lb) + 3 * DD;
        const float* hwb  = side ? rhwb : lhwb;
        const float* relw = side ? rw : lw;
        const float* attnA = p_attn + (size_t)side * M1 * DD;

        // out-proj + fused addrel -> g_x
        k_opgemm<<<dim3(DD / 128, M1 / 128), 256, SMEM_SZ>>>(
            attnA, p_opWt + (size_t)side * DD * DD, ab3, p_x, relw, side, M1, DD, DD);

        // highway layer 1: g_x -> g_xb
        k_hwgemm<<<dim3(DD / 64, M1 / 128), 256, SMEM_SZ>>>(
            p_x, p_hwWt + (size_t)(side * 2 + 0) * DD2 * DD, hwb + 0 * DD2,
            p_x, p_xb, DD, 0, DD);
        // highway layer 2: g_xb -> out (cols side*512..)
        k_hwgemm<<<dim3(DD / 64, M1 / 128), 256, SMEM_SZ>>>(
            p_xb, p_hwWt + (size_t)(side * 2 + 1) * DD2 * DD, hwb + 1 * DD2,
            p_xb, out, DD2, side * DD, DD);
    }
}